// round 1
// baseline (speedup 1.0000x reference)
#include <cuda_runtime.h>
#include <math.h>

#define NB   128   // batch
#define LQ   32    // query tokens
#define LDOC 180   // doc tokens
#define DIM  128   // feature dim
#define NW   8     // nway

// ---------------- scratch (no allocation allowed) ----------------
__device__ float g_qn[NB * LQ * DIM];     // normalized queries
__device__ float g_scores[NB * NW];       // maxsim scores

// ---------------- kernel A: L2-normalize queries over D ----------------
__global__ void qnorm_kernel(const float* __restrict__ q) {
    int vec = blockIdx.x;            // b*LQ + lq
    int d   = threadIdx.x;           // 0..127
    float v = q[vec * DIM + d];
    float s = v * v;
    #pragma unroll
    for (int o = 16; o; o >>= 1) s += __shfl_xor_sync(0xffffffffu, s, o);
    __shared__ float red[4];
    if ((threadIdx.x & 31) == 0) red[threadIdx.x >> 5] = s;
    __syncthreads();
    float tot = red[0] + red[1] + red[2] + red[3];
    g_qn[vec * DIM + d] = v / fmaxf(sqrtf(tot), 1e-12f);
}

// ---------------- kernel B: per-(b,w) MaxSim ----------------
// SMEM layout (floats):
//   sdoc  [LDOC][DIM]   XOR-swizzled doc tile (mask applied)   23040
//   sqs   [LQ][DIM]     inv-norm-scaled queries                 4096
//   sinv  [DIM]                                                  128
//   smask [192]                                                  192
// smax overlays sdoc after the main loop.
#define SM_FLOATS (LDOC * DIM + LQ * DIM + DIM + 192)
#define SM_BYTES  (SM_FLOATS * 4)

__global__ void __launch_bounds__(128, 2) maxsim_kernel(
    const float* __restrict__ doc, const int* __restrict__ mask)
{
    extern __shared__ float sm[];
    float* sdoc  = sm;
    float* sqs   = sm + LDOC * DIM;
    float* sinv  = sqs + LQ * DIM;
    float* smask = sinv + DIM;

    const int tid = threadIdx.x;
    const int bw  = blockIdx.x;       // b*NW + w
    const int b   = bw >> 3;

    // mask -> smem (as 0/1 float)
    for (int l = tid; l < LDOC; l += 128)
        smask[l] = (mask[bw * LDOC + l] != 0) ? 1.0f : 0.0f;
    __syncthreads();

    // load doc slab (masked) into swizzled smem: quad column dq stored at dq ^ (l&31)
    const float4* dg = (const float4*)(doc + (size_t)bw * LDOC * DIM);
    for (int idx = tid; idx < LDOC * (DIM / 4); idx += 128) {
        int l  = idx >> 5;            // /32 quads per row
        int dq = idx & 31;
        float4 v = dg[idx];
        float m = smask[l];
        v.x *= m; v.y *= m; v.z *= m; v.w *= m;
        int dqs = dq ^ (l & 31);
        *(float4*)&sdoc[l * DIM + dqs * 4] = v;
    }
    __syncthreads();

    // per-feature inverse norm over tokens (thread = feature d)
    {
        int d  = tid;
        int dq = d >> 2, dr = d & 3;
        float s = 0.f;
        #pragma unroll 4
        for (int l = 0; l < LDOC; l++) {
            float v = sdoc[l * DIM + ((dq ^ (l & 31)) << 2) + dr];
            s += v * v;
        }
        sinv[d] = 1.0f / fmaxf(sqrtf(s), 1e-12f);
    }
    __syncthreads();

    // scaled queries: qs[q][d] = qn[b][q][d] * inv[d]
    {
        float iv = sinv[tid];
        const float* qb = g_qn + (size_t)b * LQ * DIM;
        #pragma unroll
        for (int q = 0; q < LQ; q++)
            sqs[q * DIM + tid] = qb[q * DIM + tid] * iv;
    }
    __syncthreads();

    // main compute: thread tile = 8 queries x 6 tokens
    // qi = warp id (0..3) -> queries qi*8..qi*8+7 (warp-uniform -> broadcast loads)
    // lg = lane (0..31)   -> tokens lg + j*32, j=0..5 (j=5 valid iff lg<20)
    const int qi = tid >> 5;
    const int lg = tid & 31;
    const bool v5 = (lg + 160) < LDOC;

    int lrow[6];
    #pragma unroll
    for (int j = 0; j < 6; j++) {
        int l = lg + j * 32;
        if (j == 5 && !v5) l = 0;     // clamped; excluded from max later
        lrow[j] = l;
    }

    float acc[8][6];
    #pragma unroll
    for (int k = 0; k < 8; k++)
        #pragma unroll
        for (int j = 0; j < 6; j++) acc[k][j] = 0.f;

    const float* qbase = sqs + qi * 8 * DIM;

    #pragma unroll 2
    for (int dq = 0; dq < 32; dq++) {
        float4 qv[8];
        #pragma unroll
        for (int k = 0; k < 8; k++)
            qv[k] = *(const float4*)&qbase[k * DIM + dq * 4];
        #pragma unroll
        for (int j = 0; j < 6; j++) {
            int l = lrow[j];
            float4 dv = *(const float4*)&sdoc[l * DIM + ((dq ^ (l & 31)) << 2)];
            #pragma unroll
            for (int k = 0; k < 8; k++) {
                acc[k][j] += qv[k].x * dv.x;
                acc[k][j] += qv[k].y * dv.y;
                acc[k][j] += qv[k].z * dv.z;
                acc[k][j] += qv[k].w * dv.w;
            }
        }
    }

    // per-thread max over its 6 tokens, then cross-lane reduce per query
    __syncthreads();                  // sdoc now dead; reuse as smax
    float* smax = sdoc;               // [32 lanes][32 queries]
    #pragma unroll
    for (int k = 0; k < 8; k++) {
        float m = acc[k][0];
        m = fmaxf(m, acc[k][1]);
        m = fmaxf(m, acc[k][2]);
        m = fmaxf(m, acc[k][3]);
        m = fmaxf(m, acc[k][4]);
        if (v5) m = fmaxf(m, acc[k][5]);
        smax[lg * 32 + (qi * 8 + k)] = m;
    }
    __syncthreads();

    if (tid < 32) {
        int q = tid;
        float m = smax[q];
        #pragma unroll
        for (int i = 1; i < 32; i++) m = fmaxf(m, smax[i * 32 + q]);
        // sum over the 32 queries
        #pragma unroll
        for (int o = 16; o; o >>= 1) m += __shfl_xor_sync(0xffffffffu, m, o);
        if (tid == 0) g_scores[bw] = m;
    }
}

// ---------------- kernel C: log_softmax over NW + KL, batchmean ----------------
__global__ void finalize_kernel(const float* __restrict__ labels, float* __restrict__ out) {
    int b = threadIdx.x;              // 128 threads, one batch row each
    float s[NW], lab[NW];
    #pragma unroll
    for (int w = 0; w < NW; w++) {
        s[w]   = g_scores[b * NW + w];
        lab[w] = labels[b * NW + w];
    }
    float m = s[0];
    #pragma unroll
    for (int w = 1; w < NW; w++) m = fmaxf(m, s[w]);
    float se = 0.f;
    #pragma unroll
    for (int w = 0; w < NW; w++) se += expf(s[w] - m);
    float lse = logf(se) + m;
    float acc = 0.f;
    #pragma unroll
    for (int w = 0; w < NW; w++)
        acc += expf(lab[w]) * (lab[w] - (s[w] - lse));
    #pragma unroll
    for (int o = 16; o; o >>= 1) acc += __shfl_xor_sync(0xffffffffu, acc, o);
    __shared__ float red[4];
    if ((b & 31) == 0) red[b >> 5] = acc;
    __syncthreads();
    if (b == 0) out[0] = (red[0] + red[1] + red[2] + red[3]) / (float)NB;
}

// ---------------- launch ----------------
extern "C" void kernel_launch(void* const* d_in, const int* in_sizes, int n_in,
                              void* d_out, int out_size) {
    const float* q      = (const float*)d_in[0];
    const float* doc    = (const float*)d_in[1];
    const int*   mask   = (const int*)d_in[2];
    const float* labels = (const float*)d_in[3];
    float* out = (float*)d_out;

    cudaFuncSetAttribute(maxsim_kernel,
                         cudaFuncAttributeMaxDynamicSharedMemorySize, SM_BYTES);

    qnorm_kernel<<<NB * LQ, 128>>>(q);
    maxsim_kernel<<<NB * NW, 128, SM_BYTES>>>(doc, mask);
    finalize_kernel<<<1, NB>>>(labels, out);
}